// round 3
// baseline (speedup 1.0000x reference)
#include <cuda_runtime.h>
#include <cuda_fp16.h>

#define NB 16
#define NC 8
#define NS 128
#define SLABH 16
#define NSLAB 8
#define NSTEPS 10
#define EPSF 1e-6f
#define SX 0.0005f     // (dt/2)/dx^2
#define SY 0.001f      // dt/dy^2
#define FULLM 0xFFFFFFFFu

// shared memory layout (bytes)
#define U_OFF    0                         // float [8][16][128]  = 65536
#define AB_OFF   65536                     // half  [8][16][128]  = 32768
#define ATC_OFF  (65536 + 32768)           // half  [8][16][128]  = 32768
#define BB_OFF   (65536 + 65536)           // half  [8][20][128]  = 40960 (ext rows h0-2..h0+17)
#define BTC_OFF  (65536 + 65536 + 40960)   // half  [8][20][128]  = 40960
#define CM_OFF   (65536 + 65536 + 81920)   // float [64]          = 256
#define SMEM_TOTAL (CM_OFF + 256)          // 213248 B

static __device__ __forceinline__ unsigned smem_u32(const void* p) {
    unsigned a;
    asm("{ .reg .u64 t; cvta.to.shared.u64 t, %1; cvt.u32.u64 %0, t; }" : "=r"(a) : "l"(p));
    return a;
}
static __device__ __forceinline__ float ld_cluster(unsigned laddr, unsigned rank) {
    unsigned ra, v;
    asm volatile("mapa.shared::cluster.u32 %0, %1, %2;" : "=r"(ra) : "r"(laddr), "r"(rank));
    asm volatile("ld.shared::cluster.b32 %0, [%1];" : "=r"(v) : "r"(ra));
    return __uint_as_float(v);
}
static __device__ __forceinline__ void cluster_sync() {
    asm volatile("barrier.cluster.arrive.aligned;" ::: "memory");
    asm volatile("barrier.cluster.wait.aligned;" ::: "memory");
}

// 2-iteration Neumann solve along w; warp owns a row (4 elems/thread), mirror ends.
static __device__ __forceinline__ void xsolve2(float y[4], const float d[4],
                                               const float k[4], int l) {
    #pragma unroll
    for (int it = 0; it < 2; it++) {
        float ym1 = __shfl_up_sync(FULLM, y[3], 1);
        float yp1 = __shfl_down_sync(FULLM, y[0], 1);
        if (l == 0)  ym1 = y[0];
        if (l == 31) yp1 = y[3];
        float prev = ym1;
        #pragma unroll
        for (int e = 0; e < 4; e++) {
            float cur = y[e];
            float nxt = (e < 3) ? y[e+1] : yp1;
            float L = 2.f*cur - prev - nxt;
            y[e] = d[e] - fmaf(k[e], L, EPSF*cur);
            prev = cur;
        }
    }
}

template<int FINAL>
static __device__ __forceinline__ void xphase(float* U, const __half* Ab, const __half* Atc,
                                              float tA, float* gout, int b, int h0) {
    const int wid = threadIdx.x >> 5;
    const int l   = threadIdx.x & 31;
    #pragma unroll
    for (int i = 0; i < 4; i++) {
        const int r  = wid + 32*i;           // 0..127
        const int c  = r >> 4, hl = r & 15;
        const int base = ((c*SLABH + hl) << 7) + 4*l;
        const float4 dv = *(const float4*)&U[base];
        const float2 b0 = __half22float2(*(const __half2*)&Ab[base]);
        const float2 b1 = __half22float2(*(const __half2*)&Ab[base+2]);
        const float2 t0 = __half22float2(*(const __half2*)&Atc[base]);
        const float2 t1 = __half22float2(*(const __half2*)&Atc[base+2]);
        float k[4], d[4], y[4];
        k[0] = fminf(fmaxf(fmaf(t0.x, tA, b0.x), 1e-6f), 10.f) * SX;
        k[1] = fminf(fmaxf(fmaf(t0.y, tA, b0.y), 1e-6f), 10.f) * SX;
        k[2] = fminf(fmaxf(fmaf(t1.x, tA, b1.x), 1e-6f), 10.f) * SX;
        k[3] = fminf(fmaxf(fmaf(t1.y, tA, b1.y), 1e-6f), 10.f) * SX;
        d[0] = dv.x; d[1] = dv.y; d[2] = dv.z; d[3] = dv.w;
        y[0] = d[0]; y[1] = d[1]; y[2] = d[2]; y[3] = d[3];
        xsolve2(y, d, k, l);
        if (FINAL) {
            float4* o = (float4*)&gout[(((size_t)(b*NC + c))*NS + h0 + hl)*NS + 4*l];
            *o = make_float4(y[0], y[1], y[2], y[3]);
        } else {
            *(float4*)&U[base] = make_float4(y[0], y[1], y[2], y[3]);
        }
    }
}

static __device__ __forceinline__ void mixphase(float* U, const float* CM) {
    #pragma unroll
    for (int rep = 0; rep < 2; rep++) {
        const int p = threadIdx.x + rep*1024;   // 0..2047  (hl,w)
        const int hl = p >> 7, w = p & 127;
        float v[8];
        #pragma unroll
        for (int j = 0; j < 8; j++) v[j] = U[((j*SLABH + hl)<<7) + w];
        #pragma unroll
        for (int c = 0; c < 8; c++) {
            float acc = 0.f;
            #pragma unroll
            for (int j = 0; j < 8; j++) acc = fmaf(CM[c*8 + j], v[j], acc);
            U[((c*SLABH + hl)<<7) + w] = acc;
        }
    }
}

// Y phase: thread owns one column (c,w); 2-deep halos via DSMEM.
// ext positions 0..19 <-> global rows h0-2 .. h0+17 (own rows = pos 2..17).
static __device__ __forceinline__ void yphase(float* U, const __half* Bb, const __half* Btc,
                                              float tB, int s, unsigned u_base) {
    const int c = threadIdx.x >> 7;
    const int w = threadIdx.x & 127;
    float y[20];
    #pragma unroll
    for (int i = 2; i < 18; i++) y[i] = U[((c*SLABH + (i-2))<<7) + w];
    float dm1 = 0.f, dp0 = 0.f;
    y[0] = 0.f; y[1] = 0.f; y[18] = 0.f; y[19] = 0.f;
    if (s > 0) {
        y[0] = ld_cluster(u_base + ((((c*SLABH + 14)<<7) + w)<<2), (unsigned)(s-1));
        y[1] = ld_cluster(u_base + ((((c*SLABH + 15)<<7) + w)<<2), (unsigned)(s-1));
        dm1 = y[1];
    }
    if (s < NSLAB-1) {
        y[18] = ld_cluster(u_base + ((((c*SLABH + 0)<<7) + w)<<2), (unsigned)(s+1));
        y[19] = ld_cluster(u_base + ((((c*SLABH + 1)<<7) + w)<<2), (unsigned)(s+1));
        dp0 = y[18];
    }
    float kk[19];
    #pragma unroll
    for (int i = 1; i < 19; i++) {
        const int off = ((c*20 + i)<<7) + w;
        kk[i] = fminf(fmaxf(fmaf(__half2float(Btc[off]), tB, __half2float(Bb[off])),
                            1e-6f), 10.f) * SY;
    }
    const bool top = (s == 0), bot = (s == NSLAB-1);
    {   // iteration 0: positions 1..18
        float prev = y[0];
        #pragma unroll
        for (int i = 1; i < 19; i++) {
            const float cur = y[i];
            const float nxt = y[i+1];
            const float p2 = (top && i == 2)  ? cur : prev;
            const float n2 = (bot && i == 17) ? cur : nxt;
            float d;
            if (i == 1)       d = dm1;
            else if (i == 18) d = dp0;
            else              d = U[((c*SLABH + (i-2))<<7) + w];
            y[i] = d - fmaf(kk[i], 2.f*cur - p2 - n2, EPSF*cur);
            prev = cur;
        }
    }
    {   // iteration 1: positions 2..17
        float prev = y[1];
        #pragma unroll
        for (int i = 2; i < 18; i++) {
            const float cur = y[i];
            const float nxt = y[i+1];
            const float p2 = (top && i == 2)  ? cur : prev;
            const float n2 = (bot && i == 17) ? cur : nxt;
            const float d = U[((c*SLABH + (i-2))<<7) + w];
            y[i] = d - fmaf(kk[i], 2.f*cur - p2 - n2, EPSF*cur);
            prev = cur;
        }
    }
    cluster_sync();   // all CTAs done reading halos before anyone stores
    #pragma unroll
    for (int i = 2; i < 18; i++) U[((c*SLABH + (i-2))<<7) + w] = y[i];
}

extern "C" __global__ void __launch_bounds__(1024, 1) __cluster_dims__(NSLAB, 1, 1)
fused_adi(const float* __restrict__ gu, const float* __restrict__ gab,
          const float* __restrict__ gbb, const float* __restrict__ gatc,
          const float* __restrict__ gbtc, const float* __restrict__ gcm,
          float* __restrict__ gout)
{
    extern __shared__ __align__(16) unsigned char smem_raw[];
    float*  U   = (float*)(smem_raw + U_OFF);
    __half* Ab  = (__half*)(smem_raw + AB_OFF);
    __half* Atc = (__half*)(smem_raw + ATC_OFF);
    __half* Bb  = (__half*)(smem_raw + BB_OFF);
    __half* Btc = (__half*)(smem_raw + BTC_OFF);
    float*  CM  = (float*)(smem_raw + CM_OFF);

    const int s   = blockIdx.x;
    const int b   = blockIdx.y;
    const int h0  = s * SLABH;
    const int tid = threadIdx.x;
    const unsigned u_base = smem_u32(U);

    if (tid < 64) CM[tid] = gcm[tid];

    #pragma unroll
    for (int rep = 0; rep < 16; rep++) {
        const int p = tid + rep*1024;            // 0..16383
        const int c = p >> 11, hl = (p >> 7) & 15, w = p & 127;
        const int g = (c*NS + h0 + hl)*NS + w;
        Ab[p]  = __float2half(gab[g]);
        Atc[p] = __float2half(gatc[g]);
    }
    #pragma unroll
    for (int rep = 0; rep < 20; rep++) {
        const int p = tid + rep*1024;            // 0..20479
        const int c = p / 2560, j = (p >> 7) % 20, w = p & 127;
        const int gh = min(max(h0 - 2 + j, 0), NS-1);
        const int g = (c*NS + gh)*NS + w;
        Bb[p]  = __float2half(gbb[g]);
        Btc[p] = __float2half(gbtc[g]);
    }
    __syncthreads();

    // head: channel mix from global u, then X at t=0
    #pragma unroll
    for (int rep = 0; rep < 2; rep++) {
        const int p = tid + rep*1024;
        const int hl = p >> 7, w = p & 127;
        float v[8];
        #pragma unroll
        for (int j = 0; j < 8; j++)
            v[j] = gu[(((size_t)(b*NC + j))*NS + h0 + hl)*NS + w];
        #pragma unroll
        for (int c = 0; c < 8; c++) {
            float acc = 0.f;
            #pragma unroll
            for (int j = 0; j < 8; j++) acc = fmaf(CM[c*8 + j], v[j], acc);
            U[((c*SLABH + hl)<<7) + w] = acc;
        }
    }
    __syncthreads();
    xphase<0>(U, Ab, Atc, 0.f, nullptr, b, h0);

    for (int k = 0; k < NSTEPS; k++) {
        cluster_sync();                                   // U post-X final everywhere
        const float tB = (float)((double)k * 0.001 + 0.0005);
        yphase(U, Bb, Btc, tB, s, u_base);                // internal sync before stores
        __syncthreads();
        const float tA = (float)((double)(k+1) * 0.001);
        if (k < NSTEPS-1) {
            xphase<0>(U, Ab, Atc, tA, nullptr, b, h0);
            __syncthreads();
            mixphase(U, CM);
            __syncthreads();
            xphase<0>(U, Ab, Atc, tA, nullptr, b, h0);
        } else {
            xphase<1>(U, Ab, Atc, tA, gout, b, h0);
        }
    }
}

extern "C" void kernel_launch(void* const* d_in, const int* in_sizes, int n_in,
                              void* d_out, int out_size)
{
    (void)in_sizes; (void)n_in; (void)out_size;
    const float* u   = (const float*)d_in[0];
    const float* ab  = (const float*)d_in[1];
    const float* bb  = (const float*)d_in[2];
    const float* atc = (const float*)d_in[3];
    const float* btc = (const float*)d_in[4];
    const float* cm  = (const float*)d_in[5];

    cudaFuncSetAttribute(fused_adi, cudaFuncAttributeMaxDynamicSharedMemorySize, SMEM_TOTAL);
    dim3 grid(NSLAB, NB, 1);
    fused_adi<<<grid, 1024, SMEM_TOTAL>>>(u, ab, bb, atc, btc, cm, (float*)d_out);
}

// round 4
// speedup vs baseline: 1.6743x; 1.6743x over previous
#include <cuda_runtime.h>

#define NB 16
#define NC 8
#define NS 128
#define NSTEPS 10
#define EPSF 1e-6f
#define FULLM 0xFFFFFFFFu
#define NITER 2     // R3 evidence: 2 Neumann iterations suffice (rel_err 7e-7)

// ping state (device global: allocation-free rule)
static __device__ float g_u[NB*NC*NS*NS];

// ---------------------------------------------------------------------------
// In-register Neumann solve along w: y starts = d; NITER x  y <- d - (K*L+eps)*y
// Warp owns a full row of 128; thread owns 4 consecutive elements.
// Mirror ghosts reproduce the b=1+k boundary rows exactly.
// ---------------------------------------------------------------------------
static __device__ __forceinline__ void xsolve(float y[4], const float d[4],
                                              const float k[4], int l)
{
    #pragma unroll
    for (int it = 0; it < NITER; it++) {
        float ym1 = __shfl_up_sync(FULLM, y[3], 1);
        float yp1 = __shfl_down_sync(FULLM, y[0], 1);
        if (l == 0)  ym1 = y[0];
        if (l == 31) yp1 = y[3];
        float prev = ym1;
        #pragma unroll
        for (int e = 0; e < 4; e++) {
            float cur = y[e];
            float nxt = (e < 3) ? y[e+1] : yp1;
            float L = 2.f*cur - prev - nxt;
            y[e] = d[e] - fmaf(k[e], L, EPSF*cur);
            prev = cur;
        }
    }
}

// ---------------------------------------------------------------------------
// X-direction kernel. CTA = (b, h); warp c handles channel c's row.
// MODE 0: mix(usrc) + X          -> g_u        (head, alpha @ t=0)
// MODE 1: X + mix + X (in place) -> g_u        (body, same alpha set twice)
// MODE 2: X                      -> uout       (tail, alpha @ t=10dt)
// ---------------------------------------------------------------------------
template<int MODE>
__global__ void __launch_bounds__(256) k_x(const float* __restrict__ usrc,
                                           float* __restrict__ uout,
                                           const float* __restrict__ ab,
                                           const float* __restrict__ atc,
                                           const float* __restrict__ cm,
                                           float t)
{
    __shared__ float sm[NC][NS];
    const int tid = threadIdx.x;
    const int c = tid >> 5;
    const int l = tid & 31;
    const int b = blockIdx.x >> 7;
    const int h = blockIdx.x & 127;

    const size_t crow = (((size_t)c*NS + h))*NS + 4*l;
    const size_t urow = ((((size_t)b*NC + c)*NS + h))*NS + 4*l;

    // coefficients: k = clip(ab + atc*t, eps, 10) * (dt/2)/dx^2
    float k[4];
    {
        const float4 a4 = *(const float4*)(ab + crow);
        const float4 c4 = *(const float4*)(atc + crow);
        k[0] = fminf(fmaxf(fmaf(c4.x, t, a4.x), 1e-6f), 10.f) * 0.0005f;
        k[1] = fminf(fmaxf(fmaf(c4.y, t, a4.y), 1e-6f), 10.f) * 0.0005f;
        k[2] = fminf(fmaxf(fmaf(c4.z, t, a4.z), 1e-6f), 10.f) * 0.0005f;
        k[3] = fminf(fmaxf(fmaf(c4.w, t, a4.w), 1e-6f), 10.f) * 0.0005f;
    }

    float cmr[8];
    if (MODE != 2) {
        #pragma unroll
        for (int j = 0; j < 8; j++) cmr[j] = cm[c*8 + j];
    }

    float d[4];
    {
        const float* src = (MODE == 0) ? usrc : (const float*)g_u;
        const float4 v = *(const float4*)(src + urow);
        d[0] = v.x; d[1] = v.y; d[2] = v.z; d[3] = v.w;
    }

    if (MODE == 0) {
        // channel mix first, then solve
        *(float4*)&sm[c][4*l] = make_float4(d[0], d[1], d[2], d[3]);
        __syncthreads();
        float m[4] = {0.f, 0.f, 0.f, 0.f};
        #pragma unroll
        for (int j = 0; j < 8; j++) {
            const float4 v = *(const float4*)&sm[j][4*l];
            m[0] = fmaf(cmr[j], v.x, m[0]);
            m[1] = fmaf(cmr[j], v.y, m[1]);
            m[2] = fmaf(cmr[j], v.z, m[2]);
            m[3] = fmaf(cmr[j], v.w, m[3]);
        }
        float y[4] = {m[0], m[1], m[2], m[3]};
        xsolve(y, m, k, l);
        *(float4*)((float*)g_u + urow) = make_float4(y[0], y[1], y[2], y[3]);
    } else if (MODE == 1) {
        float y[4] = {d[0], d[1], d[2], d[3]};
        xsolve(y, d, k, l);
        *(float4*)&sm[c][4*l] = make_float4(y[0], y[1], y[2], y[3]);
        __syncthreads();
        float m[4] = {0.f, 0.f, 0.f, 0.f};
        #pragma unroll
        for (int j = 0; j < 8; j++) {
            const float4 v = *(const float4*)&sm[j][4*l];
            m[0] = fmaf(cmr[j], v.x, m[0]);
            m[1] = fmaf(cmr[j], v.y, m[1]);
            m[2] = fmaf(cmr[j], v.z, m[2]);
            m[3] = fmaf(cmr[j], v.w, m[3]);
        }
        float y2[4] = {m[0], m[1], m[2], m[3]};
        xsolve(y2, m, k, l);
        *(float4*)((float*)g_u + urow) = make_float4(y2[0], y2[1], y2[2], y2[3]);
    } else {
        float y[4] = {d[0], d[1], d[2], d[3]};
        xsolve(y, d, k, l);
        *(float4*)(uout + urow) = make_float4(y[0], y[1], y[2], y[3]);
    }
}

// ---------------------------------------------------------------------------
// Y-direction kernel. CTA = (b, c, w-tile of 32); 256 threads as
// (32 w-lanes) x (8 h-segments of 16). Thread owns 16 h in registers;
// segment halos exchanged via double-buffered smem rows. In place on g_u.
// 16h/thread (was 32) drops regs ~93 -> ~60 => 4 CTAs/SM instead of ~1.5.
// ---------------------------------------------------------------------------
__global__ void __launch_bounds__(256, 4) k_y(const float* __restrict__ bb,
                                              const float* __restrict__ btc,
                                              float t)
{
    __shared__ float sTop[NITER][8][32];
    __shared__ float sBot[NITER][8][32];
    const int wl = threadIdx.x & 31;
    const int s  = threadIdx.x >> 5;        // 0..7 segment
    const int wt = blockIdx.x & 3;
    const int c  = (blockIdx.x >> 2) & 7;
    const int b  = blockIdx.x >> 5;
    const int w  = wt*32 + wl;
    const int h0 = s*16;

    const size_t cbase = (((size_t)c*NS + h0))*NS + w;
    const size_t ubase = ((((size_t)b*NC + c)*NS + h0))*NS + w;

    float k[16], d[16], y[16];
    #pragma unroll
    for (int j = 0; j < 16; j++) {
        const float base = bb [cbase + (size_t)j*NS];
        const float tc   = btc[cbase + (size_t)j*NS];
        k[j] = fminf(fmaxf(fmaf(tc, t, base), 1e-6f), 10.f) * 0.001f;  // *DT/DY^2
        d[j] = g_u[ubase + (size_t)j*NS];
        y[j] = d[j];
    }

    #pragma unroll
    for (int it = 0; it < NITER; it++) {
        sTop[it][s][wl] = y[0];
        sBot[it][s][wl] = y[15];
        __syncthreads();
        const float ym1 = (s == 0) ? y[0]  : sBot[it][s-1][wl];
        const float yp1 = (s == 7) ? y[15] : sTop[it][s+1][wl];
        float prev = ym1;
        #pragma unroll
        for (int j = 0; j < 16; j++) {
            const float cur = y[j];
            const float nxt = (j < 15) ? y[j+1] : yp1;
            const float L = 2.f*cur - prev - nxt;
            y[j] = d[j] - fmaf(k[j], L, EPSF*cur);
            prev = cur;
        }
    }

    #pragma unroll
    for (int j = 0; j < 16; j++)
        g_u[ubase + (size_t)j*NS] = y[j];
}

// ---------------------------------------------------------------------------
// Inputs (metadata order): u, alpha_base, beta_base, alpha_time_coeff,
// beta_time_coeff, channel_mixing. Output: float32 [16,8,128,128].
// ---------------------------------------------------------------------------
extern "C" void kernel_launch(void* const* d_in, const int* in_sizes, int n_in,
                              void* d_out, int out_size)
{
    (void)in_sizes; (void)n_in; (void)out_size;
    const float* u   = (const float*)d_in[0];
    const float* ab  = (const float*)d_in[1];
    const float* bb  = (const float*)d_in[2];
    const float* atc = (const float*)d_in[3];
    const float* btc = (const float*)d_in[4];
    const float* cm  = (const float*)d_in[5];

    // head: mix + X(alpha @ t=0)
    k_x<0><<<NB*NS, 256>>>(u, nullptr, ab, atc, cm, 0.f);

    for (int k = 0; k < NSTEPS; k++) {
        const float tB = (float)((double)k * 0.001 + 0.0005);
        k_y<<<NB*NC*4, 256>>>(bb, btc, tB);
        const float tA = (float)((double)(k+1) * 0.001);
        if (k < NSTEPS-1)
            k_x<1><<<NB*NS, 256>>>(nullptr, nullptr, ab, atc, cm, tA);     // X+mix+X
        else
            k_x<2><<<NB*NS, 256>>>(nullptr, (float*)d_out, ab, atc, cm, tA); // final X
    }
}

// round 6
// speedup vs baseline: 1.6913x; 1.0102x over previous
#include <cuda_runtime.h>

#define NB 16
#define NC 8
#define NS 128
#define NSTEPS 10
#define EPSF 1e-6f
#define FULLM 0xFFFFFFFFu
#define NITER 2     // R3/R4 evidence: 2 Neumann iterations suffice (rel_err 7e-7)

// ping state (device global: allocation-free rule)
static __device__ float g_u[NB*NC*NS*NS];

// ---------------------------------------------------------------------------
// In-register Neumann solve along w: y starts = d; NITER x  y <- d - (K*L+eps)*y
// Warp owns a full row of 128; thread owns 4 consecutive elements.
// Mirror ghosts reproduce the b=1+k boundary rows exactly.
// ---------------------------------------------------------------------------
static __device__ __forceinline__ void xsolve(float y[4], const float d[4],
                                              const float k[4], int l)
{
    #pragma unroll
    for (int it = 0; it < NITER; it++) {
        float ym1 = __shfl_up_sync(FULLM, y[3], 1);
        float yp1 = __shfl_down_sync(FULLM, y[0], 1);
        if (l == 0)  ym1 = y[0];
        if (l == 31) yp1 = y[3];
        float prev = ym1;
        #pragma unroll
        for (int e = 0; e < 4; e++) {
            float cur = y[e];
            float nxt = (e < 3) ? y[e+1] : yp1;
            float L = 2.f*cur - prev - nxt;
            y[e] = d[e] - fmaf(k[e], L, EPSF*cur);
            prev = cur;
        }
    }
}

// ---------------------------------------------------------------------------
// X-direction kernel. CTA = (b, h); warp c handles channel c's row.
// MODE 0: mix(usrc) + X          -> g_u        (head, alpha @ t=0)
// MODE 1: X + mix + X (in place) -> g_u        (body, same alpha set twice)
// MODE 2: X                      -> uout       (tail, alpha @ t=10dt)
// ---------------------------------------------------------------------------
template<int MODE>
__global__ void __launch_bounds__(256) k_x(const float* __restrict__ usrc,
                                           float* __restrict__ uout,
                                           const float* __restrict__ ab,
                                           const float* __restrict__ atc,
                                           const float* __restrict__ cm,
                                           float t)
{
    __shared__ float sm[NC][NS];
    const int tid = threadIdx.x;
    const int c = tid >> 5;
    const int l = tid & 31;
    const int b = blockIdx.x >> 7;
    const int h = blockIdx.x & 127;

    const size_t crow = (((size_t)c*NS + h))*NS + 4*l;
    const size_t urow = ((((size_t)b*NC + c)*NS + h))*NS + 4*l;

    // coefficients: k = clip(ab + atc*t, eps, 10) * (dt/2)/dx^2
    float k[4];
    {
        const float4 a4 = *(const float4*)(ab + crow);
        const float4 c4 = *(const float4*)(atc + crow);
        k[0] = fminf(fmaxf(fmaf(c4.x, t, a4.x), 1e-6f), 10.f) * 0.0005f;
        k[1] = fminf(fmaxf(fmaf(c4.y, t, a4.y), 1e-6f), 10.f) * 0.0005f;
        k[2] = fminf(fmaxf(fmaf(c4.z, t, a4.z), 1e-6f), 10.f) * 0.0005f;
        k[3] = fminf(fmaxf(fmaf(c4.w, t, a4.w), 1e-6f), 10.f) * 0.0005f;
    }

    float cmr[8];
    if (MODE != 2) {
        #pragma unroll
        for (int j = 0; j < 8; j++) cmr[j] = cm[c*8 + j];
    }

    float d[4];
    {
        const float* src = (MODE == 0) ? usrc : (const float*)g_u;
        const float4 v = *(const float4*)(src + urow);
        d[0] = v.x; d[1] = v.y; d[2] = v.z; d[3] = v.w;
    }

    if (MODE == 0) {
        // channel mix first, then solve
        *(float4*)&sm[c][4*l] = make_float4(d[0], d[1], d[2], d[3]);
        __syncthreads();
        float m[4] = {0.f, 0.f, 0.f, 0.f};
        #pragma unroll
        for (int j = 0; j < 8; j++) {
            const float4 v = *(const float4*)&sm[j][4*l];
            m[0] = fmaf(cmr[j], v.x, m[0]);
            m[1] = fmaf(cmr[j], v.y, m[1]);
            m[2] = fmaf(cmr[j], v.z, m[2]);
            m[3] = fmaf(cmr[j], v.w, m[3]);
        }
        float y[4] = {m[0], m[1], m[2], m[3]};
        xsolve(y, m, k, l);
        *(float4*)((float*)g_u + urow) = make_float4(y[0], y[1], y[2], y[3]);
    } else if (MODE == 1) {
        float y[4] = {d[0], d[1], d[2], d[3]};
        xsolve(y, d, k, l);
        *(float4*)&sm[c][4*l] = make_float4(y[0], y[1], y[2], y[3]);
        __syncthreads();
        float m[4] = {0.f, 0.f, 0.f, 0.f};
        #pragma unroll
        for (int j = 0; j < 8; j++) {
            const float4 v = *(const float4*)&sm[j][4*l];
            m[0] = fmaf(cmr[j], v.x, m[0]);
            m[1] = fmaf(cmr[j], v.y, m[1]);
            m[2] = fmaf(cmr[j], v.z, m[2]);
            m[3] = fmaf(cmr[j], v.w, m[3]);
        }
        float y2[4] = {m[0], m[1], m[2], m[3]};
        xsolve(y2, m, k, l);
        *(float4*)((float*)g_u + urow) = make_float4(y2[0], y2[1], y2[2], y2[3]);
    } else {
        float y[4] = {d[0], d[1], d[2], d[3]};
        xsolve(y, d, k, l);
        *(float4*)(uout + urow) = make_float4(y[0], y[1], y[2], y[3]);
    }
}

// ---------------------------------------------------------------------------
// Y-direction kernel. CTA = (b, c, w-tile of 32); 512 threads as
// (32 w-lanes) x (16 h-segments of 8). Thread owns 8 h in registers;
// segment halos exchanged via double-buffered smem rows. In place on g_u.
// 8h/thread: ~38 regs => 3 CTAs/SM (1536 thr) instead of prior ~21 warps.
// ---------------------------------------------------------------------------
__global__ void __launch_bounds__(512, 3) k_y(const float* __restrict__ bb,
                                              const float* __restrict__ btc,
                                              float t)
{
    __shared__ float sTop[NITER][16][32];
    __shared__ float sBot[NITER][16][32];
    const int wl = threadIdx.x & 31;
    const int s  = threadIdx.x >> 5;        // 0..15 segment
    const int wt = blockIdx.x & 3;
    const int c  = (blockIdx.x >> 2) & 7;
    const int b  = blockIdx.x >> 5;
    const int w  = wt*32 + wl;
    const int h0 = s*8;

    const size_t cbase = (((size_t)c*NS + h0))*NS + w;
    const size_t ubase = ((((size_t)b*NC + c)*NS + h0))*NS + w;

    float k[8], d[8], y[8];
    #pragma unroll
    for (int j = 0; j < 8; j++) {
        const float base = bb [cbase + (size_t)j*NS];
        const float tc   = btc[cbase + (size_t)j*NS];
        k[j] = fminf(fmaxf(fmaf(tc, t, base), 1e-6f), 10.f) * 0.001f;  // *DT/DY^2
        d[j] = g_u[ubase + (size_t)j*NS];
        y[j] = d[j];
    }

    #pragma unroll
    for (int it = 0; it < NITER; it++) {
        sTop[it][s][wl] = y[0];
        sBot[it][s][wl] = y[7];
        __syncthreads();
        const float ym1 = (s == 0)  ? y[0] : sBot[it][s-1][wl];
        const float yp1 = (s == 15) ? y[7] : sTop[it][s+1][wl];
        float prev = ym1;
        #pragma unroll
        for (int j = 0; j < 8; j++) {
            const float cur = y[j];
            const float nxt = (j < 7) ? y[j+1] : yp1;
            const float L = 2.f*cur - prev - nxt;
            y[j] = d[j] - fmaf(k[j], L, EPSF*cur);
            prev = cur;
        }
    }

    #pragma unroll
    for (int j = 0; j < 8; j++)
        g_u[ubase + (size_t)j*NS] = y[j];
}

// ---------------------------------------------------------------------------
// Inputs (metadata order): u, alpha_base, beta_base, alpha_time_coeff,
// beta_time_coeff, channel_mixing. Output: float32 [16,8,128,128].
// ---------------------------------------------------------------------------
extern "C" void kernel_launch(void* const* d_in, const int* in_sizes, int n_in,
                              void* d_out, int out_size)
{
    (void)in_sizes; (void)n_in; (void)out_size;
    const float* u   = (const float*)d_in[0];
    const float* ab  = (const float*)d_in[1];
    const float* bb  = (const float*)d_in[2];
    const float* atc = (const float*)d_in[3];
    const float* btc = (const float*)d_in[4];
    const float* cm  = (const float*)d_in[5];

    // head: mix + X(alpha @ t=0)
    k_x<0><<<NB*NS, 256>>>(u, nullptr, ab, atc, cm, 0.f);

    for (int k = 0; k < NSTEPS; k++) {
        const float tB = (float)((double)k * 0.001 + 0.0005);
        k_y<<<NB*NC*4, 512>>>(bb, btc, tB);
        const float tA = (float)((double)(k+1) * 0.001);
        if (k < NSTEPS-1)
            k_x<1><<<NB*NS, 256>>>(nullptr, nullptr, ab, atc, cm, tA);     // X+mix+X
        else
            k_x<2><<<NB*NS, 256>>>(nullptr, (float*)d_out, ab, atc, cm, tA); // final X
    }
}